// round 15
// baseline (speedup 1.0000x reference)
#include <cuda_runtime.h>
#include <cuda_fp16.h>
#include <math.h>
#include <stdint.h>

#define DIMN    1024
#define NHEADS  16
#define HD      64
#define HIDDEN  4096
#define BB      4
#define SEQ     2048
#define MROWS   (BB*SEQ)   // 8192

// ---------------- scratch (device globals; no allocation allowed) ----------
__device__ __half g_h   [(size_t)MROWS*DIMN];
__device__ __half g_qkv [(size_t)MROWS*3*DIMN];
__device__ __half g_o   [(size_t)MROWS*DIMN];
__device__ float  g_x1  [(size_t)MROWS*DIMN];
__device__ __half g_ffn [(size_t)MROWS*HIDDEN];
__device__ __half g_wq  [(size_t)DIMN*3*DIMN];   // W_qkv^T (Q cols pre-scaled 0.125*log2e)
__device__ __half g_wp  [(size_t)DIMN*DIMN];
__device__ __half g_w1t [(size_t)DIMN*HIDDEN];
__device__ __half g_w2t [(size_t)DIMN*HIDDEN];

// ---------------- helpers ----------------------------------------------------
__device__ __forceinline__ uint32_t smem_u32(const void* p) {
    uint32_t a;
    asm("{ .reg .u64 t; cvta.to.shared.u64 t, %1; cvt.u32.u64 %0, t; }"
        : "=r"(a) : "l"(p));
    return a;
}
__device__ __forceinline__ void cp16(uint32_t s, const void* g) {
    asm volatile("cp.async.cg.shared.global [%0], [%1], 16;" :: "r"(s), "l"(g) : "memory");
}
__device__ __forceinline__ void mma_f16(float* d, const uint32_t* a, const uint32_t* b) {
    asm volatile(
        "mma.sync.aligned.m16n8k16.row.col.f32.f16.f16.f32 "
        "{%0,%1,%2,%3}, {%4,%5,%6,%7}, {%8,%9}, {%0,%1,%2,%3};"
        : "+f"(d[0]), "+f"(d[1]), "+f"(d[2]), "+f"(d[3])
        : "r"(a[0]), "r"(a[1]), "r"(a[2]), "r"(a[3]), "r"(b[0]), "r"(b[1]));
}
__device__ __forceinline__ void ldsm_x4(uint32_t* r, uint32_t addr) {
    asm volatile("ldmatrix.sync.aligned.m8n8.x4.shared.b16 {%0,%1,%2,%3}, [%4];"
        : "=r"(r[0]), "=r"(r[1]), "=r"(r[2]), "=r"(r[3]) : "r"(addr));
}
__device__ __forceinline__ void ldsm_x4_t(uint32_t* r, uint32_t addr) {
    asm volatile("ldmatrix.sync.aligned.m8n8.x4.trans.shared.b16 {%0,%1,%2,%3}, [%4];"
        : "=r"(r[0]), "=r"(r[1]), "=r"(r[2]), "=r"(r[3]) : "r"(addr));
}
__device__ __forceinline__ uint32_t pack_h2(float a, float b) {
    __half2 h = __floats2half2_rn(a, b);
    return *reinterpret_cast<uint32_t*>(&h);
}

// ---------------- fused weight transpose + fp16 convert (single launch) ------
#define T_QKV   (3*DIMN/32 * DIMN/32)
#define T_PROJ  (DIMN/32   * DIMN/32)
#define T_W1    (HIDDEN/32 * DIMN/32)
#define T_W2    (DIMN/32   * HIDDEN/32)
#define T_ALL   (T_QKV + T_PROJ + T_W1 + T_W2)
#define QSCALE  (0.125f * 1.4426950408889634f)   // 1/sqrt(hd) * log2(e)

__global__ __launch_bounds__(256) void cvt_all(
    const float* __restrict__ w_qkv, const float* __restrict__ w_proj,
    const float* __restrict__ w1,    const float* __restrict__ w2,
    __half* __restrict__ o_qkv, __half* __restrict__ o_proj,
    __half* __restrict__ o_w1,  __half* __restrict__ o_w2)
{
    __shared__ float tile[32][33];
    int bid = blockIdx.x;
    const float* in; __half* out;
    int K, N, tnx;
    float qscale = 1.0f;
    if (bid < T_QKV) {
        in = w_qkv; out = o_qkv; K = DIMN; N = 3*DIMN; tnx = 3*DIMN/32;
    } else if (bid < T_QKV + T_PROJ) {
        bid -= T_QKV;
        in = w_proj; out = o_proj; K = DIMN; N = DIMN; tnx = DIMN/32;
    } else if (bid < T_QKV + T_PROJ + T_W1) {
        bid -= T_QKV + T_PROJ;
        in = w1; out = o_w1; K = DIMN; N = HIDDEN; tnx = HIDDEN/32;
    } else {
        bid -= T_QKV + T_PROJ + T_W1;
        in = w2; out = o_w2; K = HIDDEN; N = DIMN; tnx = DIMN/32;
    }
    int nxt = bid % tnx, kxt = bid / tnx;
    int nx = nxt * 32, kx = kxt * 32;
    if (in == w_qkv && nx < DIMN) qscale = QSCALE;   // Q columns: fold 1/8 * log2e

    int tx = threadIdx.x, ty = threadIdx.y;
    #pragma unroll
    for (int i = 0; i < 4; i++)
        tile[ty + 8*i][tx] = in[(size_t)(kx + ty + 8*i) * N + nx + tx];
    __syncthreads();
    #pragma unroll
    for (int i = 0; i < 4; i++)
        out[(size_t)(nx + ty + 8*i) * K + kx + tx] =
            __float2half(tile[tx][ty + 8*i] * qscale);
}

// ---------------- layernorm (fp32 in -> fp16 out) ---------------------------
__device__ __forceinline__ float block_sum(float v, float* red) {
    __syncthreads();
    #pragma unroll
    for (int o = 16; o; o >>= 1) v += __shfl_down_sync(0xFFFFFFFFu, v, o);
    int w = threadIdx.x >> 5;
    if ((threadIdx.x & 31) == 0) red[w] = v;
    __syncthreads();
    if (threadIdx.x < 32) {
        v = (threadIdx.x < 8) ? red[threadIdx.x] : 0.f;
        #pragma unroll
        for (int o = 4; o; o >>= 1) v += __shfl_down_sync(0xFFFFFFFFu, v, o);
        if (threadIdx.x == 0) red[0] = v;
    }
    __syncthreads();
    return red[0];
}

__global__ __launch_bounds__(256) void ln_kernel(
    const float* __restrict__ in, const float* __restrict__ g,
    const float* __restrict__ b, __half* __restrict__ out)
{
    __shared__ float red[32];
    size_t row = blockIdx.x;
    const float4* xr = reinterpret_cast<const float4*>(in + row * DIMN);
    int t = threadIdx.x;
    float4 v = xr[t];

    float s = v.x + v.y + v.z + v.w;
    float mean = block_sum(s, red) * (1.0f / DIMN);

    float dx = v.x - mean, dy = v.y - mean, dz = v.z - mean, dw = v.w - mean;
    float sq = dx*dx + dy*dy + dz*dz + dw*dw;
    float var = block_sum(sq, red) * (1.0f / DIMN);
    float rs = rsqrtf(var + 1e-5f);

    float4 gg = reinterpret_cast<const float4*>(g)[t];
    float4 bb = reinterpret_cast<const float4*>(b)[t];
    __half2 h01 = __floats2half2_rn(dx * rs * gg.x + bb.x, dy * rs * gg.y + bb.y);
    __half2 h23 = __floats2half2_rn(dz * rs * gg.z + bb.z, dw * rs * gg.w + bb.w);
    uint2 st;
    st.x = *reinterpret_cast<uint32_t*>(&h01);
    st.y = *reinterpret_cast<uint32_t*>(&h23);
    reinterpret_cast<uint2*>(out + row * DIMN)[t] = st;
}

// ---------------- fp16 tensor-core GEMM (R8 config: 16 warps, 64x32) ---------
#define STAGES   4
#define TSTRIDE  72
#define A_HL     (256 * TSTRIDE)
#define B_HL     (128 * TSTRIDE)
#define STAGE_HL (A_HL + B_HL)
#define GEMM_SMEM (STAGES * STAGE_HL * 2)   // 221184 bytes

template<int EPI, int OUTH>
__global__ __launch_bounds__(512, 1) void gemm_f16(
    const __half* __restrict__ A, const __half* __restrict__ WT,
    const float* __restrict__ bias, const float* __restrict__ res,
    void* __restrict__ Cv, int K, int Nc)
{
    extern __shared__ __half smh[];
    const uint32_t smb = smem_u32(smh);

    const int t    = threadIdx.x;
    const int lane = t & 31;
    const int gr   = lane >> 2;
    const int qc   = lane & 3;
    const int wid  = t >> 5;
    const int wm   = wid & 3;
    const int wn   = wid >> 2;
    const int bm   = blockIdx.y * 256;
    const int bn   = blockIdx.x * 128;
    const int NC   = K >> 6;

    const uint32_t a_lo = (uint32_t)((lane & 15) * TSTRIDE + (lane >> 4) * 8) * 2;
    const uint32_t b_lo = (uint32_t)(((lane & 7) + (lane >> 4) * 8) * TSTRIDE
                                     + ((lane >> 3) & 1) * 8) * 2;

    const __half* agp[4]; uint32_t aso[4];
    #pragma unroll
    for (int i = 0; i < 4; i++) {
        int idx = t + i * 512;
        int r = idx >> 3, c8 = idx & 7;
        agp[i] = A + (size_t)(bm + r) * K + c8 * 8;
        aso[i] = (uint32_t)(r * TSTRIDE + c8 * 8) * 2;
    }
    const __half* bgp[2]; uint32_t bso[2];
    #pragma unroll
    for (int i = 0; i < 2; i++) {
        int idx = t + i * 512;
        int n = idx >> 3, c8 = idx & 7;
        bgp[i] = WT + (size_t)(bn + n) * K + c8 * 8;
        bso[i] = (uint32_t)(A_HL + n * TSTRIDE + c8 * 8) * 2;
    }

    float acc[4][4][4];
    #pragma unroll
    for (int mt = 0; mt < 4; mt++)
        #pragma unroll
        for (int nt = 0; nt < 4; nt++)
            #pragma unroll
            for (int i = 0; i < 4; i++) acc[mt][nt][i] = 0.f;

    #pragma unroll
    for (int c = 0; c < STAGES - 1; c++) {
        uint32_t so = smb + (uint32_t)(c % STAGES) * (STAGE_HL * 2);
        #pragma unroll
        for (int i = 0; i < 4; i++) cp16(so + aso[i], agp[i] + c * 64);
        #pragma unroll
        for (int i = 0; i < 2; i++) cp16(so + bso[i], bgp[i] + c * 64);
        asm volatile("cp.async.commit_group;" ::: "memory");
    }

    for (int c = 0; c < NC; c++) {
        asm volatile("cp.async.wait_group 2;" ::: "memory");
        __syncthreads();

        const int pf = c + STAGES - 1;
        if (pf < NC) {
            uint32_t so = smb + (uint32_t)(pf % STAGES) * (STAGE_HL * 2);
            #pragma unroll
            for (int i = 0; i < 4; i++) cp16(so + aso[i], agp[i] + pf * 64);
            #pragma unroll
            for (int i = 0; i < 2; i++) cp16(so + bso[i], bgp[i] + pf * 64);
        }
        asm volatile("cp.async.commit_group;" ::: "memory");

        const uint32_t asb = smb + (uint32_t)(c % STAGES) * (STAGE_HL * 2);
        const uint32_t bsb = asb + A_HL * 2;

        #pragma unroll
        for (int ks = 0; ks < 4; ks++) {
            uint32_t af[4][4], bq[2][4];
            #pragma unroll
            for (int mt = 0; mt < 4; mt++)
                ldsm_x4(af[mt], asb + a_lo +
                        (uint32_t)(((wm * 64 + mt * 16) * TSTRIDE + ks * 16) * 2));
            #pragma unroll
            for (int i = 0; i < 2; i++)
                ldsm_x4(bq[i], bsb + b_lo +
                        (uint32_t)(((wn * 32 + i * 16) * TSTRIDE + ks * 16) * 2));
            #pragma unroll
            for (int mt = 0; mt < 4; mt++)
                #pragma unroll
                for (int nt = 0; nt < 4; nt++)
                    mma_f16(acc[mt][nt], af[mt], &bq[nt >> 1][(nt & 1) * 2]);
        }
    }

    #pragma unroll
    for (int mt = 0; mt < 4; mt++) {
        #pragma unroll
        for (int half_ = 0; half_ < 2; half_++) {
            size_t row = (size_t)bm + wm * 64 + mt * 16 + gr + half_ * 8;
            #pragma unroll
            for (int nt = 0; nt < 4; nt++) {
                int col = bn + wn * 32 + nt * 8 + 2 * qc;
                float vx = acc[mt][nt][half_ * 2 + 0];
                float vy = acc[mt][nt][half_ * 2 + 1];
                if (EPI >= 1) {
                    vx += bias[col];
                    vy += bias[col + 1];
                }
                if (EPI == 1) {
                    const float2 rr = *reinterpret_cast<const float2*>(res + row * Nc + col);
                    vx += rr.x; vy += rr.y;
                }
                if (EPI == 2) {
                    const float kk = 0.70710678118654752f;
                    vx = 0.5f * vx * (1.f + erff(vx * kk));
                    vy = 0.5f * vy * (1.f + erff(vy * kk));
                }
                if (OUTH) {
                    __half2 h = __floats2half2_rn(vx, vy);
                    *reinterpret_cast<__half2*>((__half*)Cv + row * Nc + col) = h;
                } else {
                    float2 o; o.x = vx; o.y = vy;
                    *reinterpret_cast<float2*>((float*)Cv + row * Nc + col) = o;
                }
            }
        }
    }
}

// ---------------- fp16 flash attention (exp2 softmax, cond. rescale) --------
// Q pre-scaled by 0.125*log2e in the QKV weights -> S already in log2 domain.
#define KST 72
#define BUF_HL (2 * 64 * KST)

__global__ __launch_bounds__(256) void attn_f16(
    const __half* __restrict__ qkv, __half* __restrict__ out)
{
    __shared__ __half sKV[2][BUF_HL];

    const int t = threadIdx.x, lane = t & 31, wid = t >> 5;
    const int gr = lane >> 2, qc = lane & 3;

    const uint32_t sb0 = smem_u32(sKV);
    const uint32_t b_lo_k = (uint32_t)(((lane & 7) + (lane >> 4) * 8) * KST
                                       + ((lane >> 3) & 1) * 8) * 2;
    const uint32_t b_lo_v = (uint32_t)((lane & 15) * KST + (lane >> 4) * 8) * 2;

    const int bh = blockIdx.x;
    const int b  = bh / NHEADS;
    const int h  = bh % NHEADS;
    const int q0 = blockIdx.y * 128;
    const int r0 = q0 + wid * 16 + gr;

    const int krow0 = t >> 3,           kc80 = t & 7;
    const int krow1 = (t + 256) >> 3,   kc81 = (t + 256) & 7;
    const __half* kgp0 = qkv + ((size_t)(b * SEQ + krow0)) * (3 * DIMN) + DIMN + h * HD + kc80 * 8;
    const __half* kgp1 = qkv + ((size_t)(b * SEQ + krow1)) * (3 * DIMN) + DIMN + h * HD + kc81 * 8;
    const __half* vgp0 = kgp0 + DIMN;
    const __half* vgp1 = kgp1 + DIMN;
    const uint32_t kso0 = (uint32_t)(krow0 * KST + kc80 * 8) * 2;
    const uint32_t kso1 = (uint32_t)(krow1 * KST + kc81 * 8) * 2;
    const uint32_t vso0 = kso0 + (uint32_t)(64 * KST) * 2;
    const uint32_t vso1 = kso1 + (uint32_t)(64 * KST) * 2;
    const size_t tile_step = (size_t)64 * (3 * DIMN);

    uint32_t aq[4][4];
    {
        const __half* Q0 = qkv + ((size_t)(b * SEQ + r0)) * (3 * DIMN) + h * HD;
        const __half* Q8 = Q0 + 8 * (3 * DIMN);
        #pragma unroll
        for (int kc = 0; kc < 4; kc++) {
            int kb = kc * 16 + 2 * qc;
            aq[kc][0] = *reinterpret_cast<const uint32_t*>(Q0 + kb);
            aq[kc][1] = *reinterpret_cast<const uint32_t*>(Q8 + kb);
            aq[kc][2] = *reinterpret_cast<const uint32_t*>(Q0 + kb + 8);
            aq[kc][3] = *reinterpret_cast<const uint32_t*>(Q8 + kb + 8);
        }
    }

    float m0 = -1e30f, m1 = -1e30f, l0 = 0.f, l1 = 0.f;
    float o[8][4];
    #pragma unroll
    for (int nt = 0; nt < 8; nt++)
        #pragma unroll
        for (int i = 0; i < 4; i++) o[nt][i] = 0.f;

    // prologue: tile 0 -> buffer 0
    {
        uint32_t sb = sb0;
        cp16(sb + kso0, kgp0);
        cp16(sb + kso1, kgp1);
        cp16(sb + vso0, vgp0);
        cp16(sb + vso1, vgp1);
        asm volatile("cp.async.commit_group;" ::: "memory");
    }

    const int NT = SEQ / 64;
    for (int kt = 0; kt < NT; kt++) {
        asm volatile("cp.async.wait_group 0;" ::: "memory");
        __syncthreads();

        if (kt + 1 < NT) {
            size_t off = (size_t)(kt + 1) * tile_step;
            uint32_t sb = sb0 + (uint32_t)(((kt + 1) & 1) * BUF_HL) * 2;
            cp16(sb + kso0, kgp0 + off);
            cp16(sb + kso1, kgp1 + off);
            cp16(sb + vso0, vgp0 + off);
            cp16(sb + vso1, vgp1 + off);
        }
        asm volatile("cp.async.commit_group;" ::: "memory");

        const uint32_t sKb = sb0 + (uint32_t)((kt & 1) * BUF_HL) * 2;
        const uint32_t sVb = sKb + (uint32_t)(64 * KST) * 2;

        // S = Q K^T (16 x 64 per warp), values in log2 domain
        float s[8][4];
        #pragma unroll
        for (int nt = 0; nt < 8; nt++)
            #pragma unroll
            for (int i = 0; i < 4; i++) s[nt][i] = 0.f;
        #pragma unroll
        for (int kc = 0; kc < 4; kc++) {
            #pragma unroll
            for (int i = 0; i < 4; i++) {
                uint32_t bq[4];
                ldsm_x4(bq, sKb + b_lo_k + (uint32_t)(((i * 16) * KST + kc * 16) * 2));
                mma_f16(s[2*i],   aq[kc], bq);
                mma_f16(s[2*i+1], aq[kc], bq + 2);
            }
        }

        // online softmax (base-2)
        float mx0 = -1e30f, mx1 = -1e30f;
        #pragma unroll
        for (int nt = 0; nt < 8; nt++) {
            mx0 = fmaxf(mx0, fmaxf(s[nt][0], s[nt][1]));
            mx1 = fmaxf(mx1, fmaxf(s[nt][2], s[nt][3]));
        }
        mx0 = fmaxf(mx0, __shfl_xor_sync(0xFFFFFFFFu, mx0, 1));
        mx0 = fmaxf(mx0, __shfl_xor_sync(0xFFFFFFFFu, mx0, 2));
        mx1 = fmaxf(mx1, __shfl_xor_sync(0xFFFFFFFFu, mx1, 1));
        mx1 = fmaxf(mx1, __shfl_xor_sync(0xFFFFFFFFu, mx1, 2));

        if (mx0 > m0 || mx1 > m1) {        // new max -> rescale (rare after warmup)
            float mn0 = fmaxf(m0, mx0), mn1 = fmaxf(m1, mx1);
            float al0 = exp2f(m0 - mn0), al1 = exp2f(m1 - mn1);
            m0 = mn0; m1 = mn1;
            l0 *= al0; l1 *= al1;
            #pragma unroll
            for (int nt = 0; nt < 8; nt++) {
                o[nt][0] *= al0; o[nt][1] *= al0;
                o[nt][2] *= al1; o[nt][3] *= al1;
            }
        }

        float sum0 = 0.f, sum1 = 0.f;
        #pragma unroll
        for (int nt = 0; nt < 8; nt++) {
            s[nt][0] = exp2f(s[nt][0] - m0);
            s[nt][1] = exp2f(s[nt][1] - m0);
            s[nt][2] = exp2f(s[nt][2] - m1);
            s[nt][3] = exp2f(s[nt][3] - m1);
            sum0 += s[nt][0] + s[nt][1];
            sum1 += s[nt][2] + s[nt][3];
        }
        sum0 += __shfl_xor_sync(0xFFFFFFFFu, sum0, 1);
        sum0 += __shfl_xor_sync(0xFFFFFFFFu, sum0, 2);
        sum1 += __shfl_xor_sync(0xFFFFFFFFu, sum1, 1);
        sum1 += __shfl_xor_sync(0xFFFFFFFFu, sum1, 2);
        l0 += sum0;
        l1 += sum1;

        // O += P V : P from registers; V via ldmatrix.trans
        #pragma unroll
        for (int kc = 0; kc < 4; kc++) {
            uint32_t ap[4];
            ap[0] = pack_h2(s[2*kc  ][0], s[2*kc  ][1]);
            ap[1] = pack_h2(s[2*kc  ][2], s[2*kc  ][3]);
            ap[2] = pack_h2(s[2*kc+1][0], s[2*kc+1][1]);
            ap[3] = pack_h2(s[2*kc+1][2], s[2*kc+1][3]);
            #pragma unroll
            for (int i = 0; i < 4; i++) {
                uint32_t bq[4];
                ldsm_x4_t(bq, sVb + b_lo_v +
                          (uint32_t)(((kc * 16) * KST + i * 16) * 2));
                mma_f16(o[2*i],   ap, bq);
                mma_f16(o[2*i+1], ap, bq + 2);
            }
        }
    }

    // normalize + fp16 store
    float inv0 = 1.0f / l0, inv1 = 1.0f / l1;
    __half* O0 = out + ((size_t)(b * SEQ + r0)) * DIMN + h * HD;
    __half* O8 = O0 + 8 * DIMN;
    #pragma unroll
    for (int nt = 0; nt < 8; nt++) {
        int col = nt * 8 + 2 * qc;
        *reinterpret_cast<__half2*>(O0 + col) =
            __floats2half2_rn(o[nt][0] * inv0, o[nt][1] * inv0);
        *reinterpret_cast<__half2*>(O8 + col) =
            __floats2half2_rn(o[nt][2] * inv1, o[nt][3] * inv1);
    }
}

// ---------------- launch ----------------------------------------------------
extern "C" void kernel_launch(void* const* d_in, const int* in_sizes, int n_in,
                              void* d_out, int out_size)
{
    (void)in_sizes; (void)n_in; (void)out_size;
    const float* x      = (const float*)d_in[0];
    const float* w_qkv  = (const float*)d_in[1];
    const float* w_proj = (const float*)d_in[2];
    const float* b_proj = (const float*)d_in[3];
    const float* ln1_g  = (const float*)d_in[4];
    const float* ln1_b  = (const float*)d_in[5];
    const float* w1     = (const float*)d_in[6];
    const float* b1     = (const float*)d_in[7];
    const float* w2     = (const float*)d_in[8];
    const float* b2     = (const float*)d_in[9];
    const float* ln2_g  = (const float*)d_in[10];
    const float* ln2_b  = (const float*)d_in[11];
    float* out = (float*)d_out;

    __half *p_h, *p_qkv, *p_o, *p_ffn, *p_wq, *p_wp, *p_w1, *p_w2;
    float *p_x1;
    cudaGetSymbolAddress((void**)&p_h,   g_h);
    cudaGetSymbolAddress((void**)&p_qkv, g_qkv);
    cudaGetSymbolAddress((void**)&p_o,   g_o);
    cudaGetSymbolAddress((void**)&p_x1,  g_x1);
    cudaGetSymbolAddress((void**)&p_ffn, g_ffn);
    cudaGetSymbolAddress((void**)&p_wq,  g_wq);
    cudaGetSymbolAddress((void**)&p_wp,  g_wp);
    cudaGetSymbolAddress((void**)&p_w1,  g_w1t);
    cudaGetSymbolAddress((void**)&p_w2,  g_w2t);

    cudaFuncSetAttribute(gemm_f16<0,1>, cudaFuncAttributeMaxDynamicSharedMemorySize, GEMM_SMEM);
    cudaFuncSetAttribute(gemm_f16<1,0>, cudaFuncAttributeMaxDynamicSharedMemorySize, GEMM_SMEM);
    cudaFuncSetAttribute(gemm_f16<2,1>, cudaFuncAttributeMaxDynamicSharedMemorySize, GEMM_SMEM);

    // 0) all weight transposes + fp16 convert in ONE launch
    cvt_all<<<T_ALL, dim3(32,8)>>>(w_qkv, w_proj, w1, w2, p_wq, p_wp, p_w1, p_w2);

    // 1) LN1 (fp16 out)
    ln_kernel<<<MROWS, 256>>>(x, ln1_g, ln1_b, p_h);
    // 2) QKV projection (fp16 out; Q columns pre-scaled by 0.125*log2e)
    gemm_f16<0,1><<<dim3(3*DIMN/128, MROWS/256), 512, GEMM_SMEM>>>(p_h, p_wq, nullptr, nullptr, p_qkv, DIMN, 3*DIMN);
    // 3) attention (fp16 out)
    attn_f16<<<dim3(BB*NHEADS, SEQ/128), 256>>>(p_qkv, p_o);
    // 4) output projection + bias + residual (fp32 out)
    gemm_f16<1,0><<<dim3(DIMN/128, MROWS/256), 512, GEMM_SMEM>>>(p_o, p_wp, b_proj, x, p_x1, DIMN, DIMN);
    // 5) LN2 (fp16 out)
    ln_kernel<<<MROWS, 256>>>(p_x1, ln2_g, ln2_b, p_h);
    // 6) FFN up + GELU (fp16 out)
    gemm_f16<2,1><<<dim3(HIDDEN/128, MROWS/256), 512, GEMM_SMEM>>>(p_h, p_w1, b1, nullptr, p_ffn, DIMN, HIDDEN);
    // 7) FFN down + bias + residual (fp32 out)
    gemm_f16<1,0><<<dim3(DIMN/128, MROWS/256), 512, GEMM_SMEM>>>(p_ffn, p_w2, b2, p_x1, out, HIDDEN, DIMN);
}

// round 16
// speedup vs baseline: 1.0117x; 1.0117x over previous
#include <cuda_runtime.h>
#include <cuda_fp16.h>
#include <math.h>
#include <stdint.h>

#define DIMN    1024
#define NHEADS  16
#define HD      64
#define HIDDEN  4096
#define BB      4
#define SEQ     2048
#define MROWS   (BB*SEQ)   // 8192

// ---------------- scratch (device globals; no allocation allowed) ----------
__device__ __half g_h   [(size_t)MROWS*DIMN];
__device__ __half g_qkv [(size_t)MROWS*3*DIMN];
__device__ __half g_o   [(size_t)MROWS*DIMN];
__device__ float  g_x1  [(size_t)MROWS*DIMN];
__device__ __half g_ffn [(size_t)MROWS*HIDDEN];
__device__ __half g_wq  [(size_t)DIMN*3*DIMN];   // W_qkv^T (Q cols pre-scaled 0.125*log2e)
__device__ __half g_wp  [(size_t)DIMN*DIMN];
__device__ __half g_w1t [(size_t)DIMN*HIDDEN];
__device__ __half g_w2t [(size_t)DIMN*HIDDEN];

// ---------------- helpers ----------------------------------------------------
__device__ __forceinline__ uint32_t smem_u32(const void* p) {
    uint32_t a;
    asm("{ .reg .u64 t; cvta.to.shared.u64 t, %1; cvt.u32.u64 %0, t; }"
        : "=r"(a) : "l"(p));
    return a;
}
__device__ __forceinline__ void cp16(uint32_t s, const void* g) {
    asm volatile("cp.async.cg.shared.global [%0], [%1], 16;" :: "r"(s), "l"(g) : "memory");
}
__device__ __forceinline__ void mma_f16(float* d, const uint32_t* a, const uint32_t* b) {
    asm volatile(
        "mma.sync.aligned.m16n8k16.row.col.f32.f16.f16.f32 "
        "{%0,%1,%2,%3}, {%4,%5,%6,%7}, {%8,%9}, {%0,%1,%2,%3};"
        : "+f"(d[0]), "+f"(d[1]), "+f"(d[2]), "+f"(d[3])
        : "r"(a[0]), "r"(a[1]), "r"(a[2]), "r"(a[3]), "r"(b[0]), "r"(b[1]));
}
__device__ __forceinline__ void ldsm_x4(uint32_t* r, uint32_t addr) {
    asm volatile("ldmatrix.sync.aligned.m8n8.x4.shared.b16 {%0,%1,%2,%3}, [%4];"
        : "=r"(r[0]), "=r"(r[1]), "=r"(r[2]), "=r"(r[3]) : "r"(addr));
}
__device__ __forceinline__ void ldsm_x4_t(uint32_t* r, uint32_t addr) {
    asm volatile("ldmatrix.sync.aligned.m8n8.x4.trans.shared.b16 {%0,%1,%2,%3}, [%4];"
        : "=r"(r[0]), "=r"(r[1]), "=r"(r[2]), "=r"(r[3]) : "r"(addr));
}
__device__ __forceinline__ uint32_t pack_h2(float a, float b) {
    __half2 h = __floats2half2_rn(a, b);
    return *reinterpret_cast<uint32_t*>(&h);
}

// ---------------- fused weight transpose + fp16 convert (single launch) ------
#define T_QKV   (3*DIMN/32 * DIMN/32)
#define T_PROJ  (DIMN/32   * DIMN/32)
#define T_W1    (HIDDEN/32 * DIMN/32)
#define T_W2    (DIMN/32   * HIDDEN/32)
#define T_ALL   (T_QKV + T_PROJ + T_W1 + T_W2)
#define QSCALE  (0.125f * 1.4426950408889634f)   // 1/sqrt(hd) * log2(e)

__global__ __launch_bounds__(256) void cvt_all(
    const float* __restrict__ w_qkv, const float* __restrict__ w_proj,
    const float* __restrict__ w1,    const float* __restrict__ w2,
    __half* __restrict__ o_qkv, __half* __restrict__ o_proj,
    __half* __restrict__ o_w1,  __half* __restrict__ o_w2)
{
    __shared__ float tile[32][33];
    int bid = blockIdx.x;
    const float* in; __half* out;
    int K, N, tnx;
    float qscale = 1.0f;
    if (bid < T_QKV) {
        in = w_qkv; out = o_qkv; K = DIMN; N = 3*DIMN; tnx = 3*DIMN/32;
    } else if (bid < T_QKV + T_PROJ) {
        bid -= T_QKV;
        in = w_proj; out = o_proj; K = DIMN; N = DIMN; tnx = DIMN/32;
    } else if (bid < T_QKV + T_PROJ + T_W1) {
        bid -= T_QKV + T_PROJ;
        in = w1; out = o_w1; K = DIMN; N = HIDDEN; tnx = HIDDEN/32;
    } else {
        bid -= T_QKV + T_PROJ + T_W1;
        in = w2; out = o_w2; K = HIDDEN; N = DIMN; tnx = DIMN/32;
    }
    int nxt = bid % tnx, kxt = bid / tnx;
    int nx = nxt * 32, kx = kxt * 32;
    if (in == w_qkv && nx < DIMN) qscale = QSCALE;

    int tx = threadIdx.x, ty = threadIdx.y;
    #pragma unroll
    for (int i = 0; i < 4; i++)
        tile[ty + 8*i][tx] = in[(size_t)(kx + ty + 8*i) * N + nx + tx];
    __syncthreads();
    #pragma unroll
    for (int i = 0; i < 4; i++)
        out[(size_t)(nx + ty + 8*i) * K + kx + tx] =
            __float2half(tile[tx][ty + 8*i] * qscale);
}

// ---------------- layernorm (fp32 in -> fp16 out) ---------------------------
__device__ __forceinline__ float block_sum(float v, float* red) {
    __syncthreads();
    #pragma unroll
    for (int o = 16; o; o >>= 1) v += __shfl_down_sync(0xFFFFFFFFu, v, o);
    int w = threadIdx.x >> 5;
    if ((threadIdx.x & 31) == 0) red[w] = v;
    __syncthreads();
    if (threadIdx.x < 32) {
        v = (threadIdx.x < 8) ? red[threadIdx.x] : 0.f;
        #pragma unroll
        for (int o = 4; o; o >>= 1) v += __shfl_down_sync(0xFFFFFFFFu, v, o);
        if (threadIdx.x == 0) red[0] = v;
    }
    __syncthreads();
    return red[0];
}

__global__ __launch_bounds__(256) void ln_kernel(
    const float* __restrict__ in, const float* __restrict__ g,
    const float* __restrict__ b, __half* __restrict__ out)
{
    __shared__ float red[32];
    size_t row = blockIdx.x;
    const float4* xr = reinterpret_cast<const float4*>(in + row * DIMN);
    int t = threadIdx.x;
    float4 v = xr[t];

    float s = v.x + v.y + v.z + v.w;
    float mean = block_sum(s, red) * (1.0f / DIMN);

    float dx = v.x - mean, dy = v.y - mean, dz = v.z - mean, dw = v.w - mean;
    float sq = dx*dx + dy*dy + dz*dz + dw*dw;
    float var = block_sum(sq, red) * (1.0f / DIMN);
    float rs = rsqrtf(var + 1e-5f);

    float4 gg = reinterpret_cast<const float4*>(g)[t];
    float4 bb = reinterpret_cast<const float4*>(b)[t];
    __half2 h01 = __floats2half2_rn(dx * rs * gg.x + bb.x, dy * rs * gg.y + bb.y);
    __half2 h23 = __floats2half2_rn(dz * rs * gg.z + bb.z, dw * rs * gg.w + bb.w);
    uint2 st;
    st.x = *reinterpret_cast<uint32_t*>(&h01);
    st.y = *reinterpret_cast<uint32_t*>(&h23);
    reinterpret_cast<uint2*>(out + row * DIMN)[t] = st;
}

// ---------------- fp16 tensor-core GEMM (R8 config: 16 warps, 64x32) ---------
#define STAGES   4
#define TSTRIDE  72
#define A_HL     (256 * TSTRIDE)
#define B_HL     (128 * TSTRIDE)
#define STAGE_HL (A_HL + B_HL)
#define GEMM_SMEM (STAGES * STAGE_HL * 2)   // 221184 bytes

template<int EPI, int OUTH>
__global__ __launch_bounds__(512, 1) void gemm_f16(
    const __half* __restrict__ A, const __half* __restrict__ WT,
    const float* __restrict__ bias, const float* __restrict__ res,
    void* __restrict__ Cv, int K, int Nc)
{
    extern __shared__ __half smh[];
    const uint32_t smb = smem_u32(smh);

    const int t    = threadIdx.x;
    const int lane = t & 31;
    const int gr   = lane >> 2;
    const int qc   = lane & 3;
    const int wid  = t >> 5;
    const int wm   = wid & 3;
    const int wn   = wid >> 2;
    const int bm   = blockIdx.y * 256;
    const int bn   = blockIdx.x * 128;
    const int NC   = K >> 6;

    const uint32_t a_lo = (uint32_t)((lane & 15) * TSTRIDE + (lane >> 4) * 8) * 2;
    const uint32_t b_lo = (uint32_t)(((lane & 7) + (lane >> 4) * 8) * TSTRIDE
                                     + ((lane >> 3) & 1) * 8) * 2;

    const __half* agp[4]; uint32_t aso[4];
    #pragma unroll
    for (int i = 0; i < 4; i++) {
        int idx = t + i * 512;
        int r = idx >> 3, c8 = idx & 7;
        agp[i] = A + (size_t)(bm + r) * K + c8 * 8;
        aso[i] = (uint32_t)(r * TSTRIDE + c8 * 8) * 2;
    }
    const __half* bgp[2]; uint32_t bso[2];
    #pragma unroll
    for (int i = 0; i < 2; i++) {
        int idx = t + i * 512;
        int n = idx >> 3, c8 = idx & 7;
        bgp[i] = WT + (size_t)(bn + n) * K + c8 * 8;
        bso[i] = (uint32_t)(A_HL + n * TSTRIDE + c8 * 8) * 2;
    }

    float acc[4][4][4];
    #pragma unroll
    for (int mt = 0; mt < 4; mt++)
        #pragma unroll
        for (int nt = 0; nt < 4; nt++)
            #pragma unroll
            for (int i = 0; i < 4; i++) acc[mt][nt][i] = 0.f;

    #pragma unroll
    for (int c = 0; c < STAGES - 1; c++) {
        uint32_t so = smb + (uint32_t)(c % STAGES) * (STAGE_HL * 2);
        #pragma unroll
        for (int i = 0; i < 4; i++) cp16(so + aso[i], agp[i] + c * 64);
        #pragma unroll
        for (int i = 0; i < 2; i++) cp16(so + bso[i], bgp[i] + c * 64);
        asm volatile("cp.async.commit_group;" ::: "memory");
    }

    for (int c = 0; c < NC; c++) {
        asm volatile("cp.async.wait_group 2;" ::: "memory");
        __syncthreads();

        const int pf = c + STAGES - 1;
        if (pf < NC) {
            uint32_t so = smb + (uint32_t)(pf % STAGES) * (STAGE_HL * 2);
            #pragma unroll
            for (int i = 0; i < 4; i++) cp16(so + aso[i], agp[i] + pf * 64);
            #pragma unroll
            for (int i = 0; i < 2; i++) cp16(so + bso[i], bgp[i] + pf * 64);
        }
        asm volatile("cp.async.commit_group;" ::: "memory");

        const uint32_t asb = smb + (uint32_t)(c % STAGES) * (STAGE_HL * 2);
        const uint32_t bsb = asb + A_HL * 2;

        #pragma unroll
        for (int ks = 0; ks < 4; ks++) {
            uint32_t af[4][4], bq[2][4];
            #pragma unroll
            for (int mt = 0; mt < 4; mt++)
                ldsm_x4(af[mt], asb + a_lo +
                        (uint32_t)(((wm * 64 + mt * 16) * TSTRIDE + ks * 16) * 2));
            #pragma unroll
            for (int i = 0; i < 2; i++)
                ldsm_x4(bq[i], bsb + b_lo +
                        (uint32_t)(((wn * 32 + i * 16) * TSTRIDE + ks * 16) * 2));
            #pragma unroll
            for (int mt = 0; mt < 4; mt++)
                #pragma unroll
                for (int nt = 0; nt < 4; nt++)
                    mma_f16(acc[mt][nt], af[mt], &bq[nt >> 1][(nt & 1) * 2]);
        }
    }

    #pragma unroll
    for (int mt = 0; mt < 4; mt++) {
        #pragma unroll
        for (int half_ = 0; half_ < 2; half_++) {
            size_t row = (size_t)bm + wm * 64 + mt * 16 + gr + half_ * 8;
            #pragma unroll
            for (int nt = 0; nt < 4; nt++) {
                int col = bn + wn * 32 + nt * 8 + 2 * qc;
                float vx = acc[mt][nt][half_ * 2 + 0];
                float vy = acc[mt][nt][half_ * 2 + 1];
                if (EPI >= 1) {
                    vx += bias[col];
                    vy += bias[col + 1];
                }
                if (EPI == 1) {
                    const float2 rr = *reinterpret_cast<const float2*>(res + row * Nc + col);
                    vx += rr.x; vy += rr.y;
                }
                if (EPI == 2) {
                    const float kk = 0.70710678118654752f;
                    vx = 0.5f * vx * (1.f + erff(vx * kk));
                    vy = 0.5f * vy * (1.f + erff(vy * kk));
                }
                if (OUTH) {
                    __half2 h = __floats2half2_rn(vx, vy);
                    *reinterpret_cast<__half2*>((__half*)Cv + row * Nc + col) = h;
                } else {
                    float2 o; o.x = vx; o.y = vy;
                    *reinterpret_cast<float2*>((float*)Cv + row * Nc + col) = o;
                }
            }
        }
    }
}

// ---------------- fp16 flash attention (exp2 softmax, unconditional rescale) -
// Q pre-scaled by 0.125*log2e in the QKV weights -> S already in log2 domain.
#define KST 72
#define BUF_HL (2 * 64 * KST)

__global__ __launch_bounds__(256) void attn_f16(
    const __half* __restrict__ qkv, __half* __restrict__ out)
{
    __shared__ __half sKV[2][BUF_HL];

    const int t = threadIdx.x, lane = t & 31, wid = t >> 5;
    const int gr = lane >> 2, qc = lane & 3;

    const uint32_t sb0 = smem_u32(sKV);
    const uint32_t b_lo_k = (uint32_t)(((lane & 7) + (lane >> 4) * 8) * KST
                                       + ((lane >> 3) & 1) * 8) * 2;
    const uint32_t b_lo_v = (uint32_t)((lane & 15) * KST + (lane >> 4) * 8) * 2;

    const int bh = blockIdx.x;
    const int b  = bh / NHEADS;
    const int h  = bh % NHEADS;
    const int q0 = blockIdx.y * 128;
    const int r0 = q0 + wid * 16 + gr;

    const int krow0 = t >> 3,           kc80 = t & 7;
    const int krow1 = (t + 256) >> 3,   kc81 = (t + 256) & 7;
    const __half* kgp0 = qkv + ((size_t)(b * SEQ + krow0)) * (3 * DIMN) + DIMN + h * HD + kc80 * 8;
    const __half* kgp1 = qkv + ((size_t)(b * SEQ + krow1)) * (3 * DIMN) + DIMN + h * HD + kc81 * 8;
    const __half* vgp0 = kgp0 + DIMN;
    const __half* vgp1 = kgp1 + DIMN;
    const uint32_t kso0 = (uint32_t)(krow0 * KST + kc80 * 8) * 2;
    const uint32_t kso1 = (uint32_t)(krow1 * KST + kc81 * 8) * 2;
    const uint32_t vso0 = kso0 + (uint32_t)(64 * KST) * 2;
    const uint32_t vso1 = kso1 + (uint32_t)(64 * KST) * 2;
    const size_t tile_step = (size_t)64 * (3 * DIMN);

    uint32_t aq[4][4];
    {
        const __half* Q0 = qkv + ((size_t)(b * SEQ + r0)) * (3 * DIMN) + h * HD;
        const __half* Q8 = Q0 + 8 * (3 * DIMN);
        #pragma unroll
        for (int kc = 0; kc < 4; kc++) {
            int kb = kc * 16 + 2 * qc;
            aq[kc][0] = *reinterpret_cast<const uint32_t*>(Q0 + kb);
            aq[kc][1] = *reinterpret_cast<const uint32_t*>(Q8 + kb);
            aq[kc][2] = *reinterpret_cast<const uint32_t*>(Q0 + kb + 8);
            aq[kc][3] = *reinterpret_cast<const uint32_t*>(Q8 + kb + 8);
        }
    }

    float m0 = -1e30f, m1 = -1e30f, l0 = 0.f, l1 = 0.f;
    float o[8][4];
    #pragma unroll
    for (int nt = 0; nt < 8; nt++)
        #pragma unroll
        for (int i = 0; i < 4; i++) o[nt][i] = 0.f;

    // prologue: tile 0 -> buffer 0
    {
        uint32_t sb = sb0;
        cp16(sb + kso0, kgp0);
        cp16(sb + kso1, kgp1);
        cp16(sb + vso0, vgp0);
        cp16(sb + vso1, vgp1);
        asm volatile("cp.async.commit_group;" ::: "memory");
    }

    const int NT = SEQ / 64;
    for (int kt = 0; kt < NT; kt++) {
        asm volatile("cp.async.wait_group 0;" ::: "memory");
        __syncthreads();

        if (kt + 1 < NT) {
            size_t off = (size_t)(kt + 1) * tile_step;
            uint32_t sb = sb0 + (uint32_t)(((kt + 1) & 1) * BUF_HL) * 2;
            cp16(sb + kso0, kgp0 + off);
            cp16(sb + kso1, kgp1 + off);
            cp16(sb + vso0, vgp0 + off);
            cp16(sb + vso1, vgp1 + off);
        }
        asm volatile("cp.async.commit_group;" ::: "memory");

        const uint32_t sKb = sb0 + (uint32_t)((kt & 1) * BUF_HL) * 2;
        const uint32_t sVb = sKb + (uint32_t)(64 * KST) * 2;

        // S = Q K^T (16 x 64 per warp), values in log2 domain
        float s[8][4];
        #pragma unroll
        for (int nt = 0; nt < 8; nt++)
            #pragma unroll
            for (int i = 0; i < 4; i++) s[nt][i] = 0.f;
        #pragma unroll
        for (int kc = 0; kc < 4; kc++) {
            #pragma unroll
            for (int i = 0; i < 4; i++) {
                uint32_t bq[4];
                ldsm_x4(bq, sKb + b_lo_k + (uint32_t)(((i * 16) * KST + kc * 16) * 2));
                mma_f16(s[2*i],   aq[kc], bq);
                mma_f16(s[2*i+1], aq[kc], bq + 2);
            }
        }

        // online softmax (base-2, unconditional rescale — no divergence)
        float mx0 = -1e30f, mx1 = -1e30f;
        #pragma unroll
        for (int nt = 0; nt < 8; nt++) {
            mx0 = fmaxf(mx0, fmaxf(s[nt][0], s[nt][1]));
            mx1 = fmaxf(mx1, fmaxf(s[nt][2], s[nt][3]));
        }
        mx0 = fmaxf(mx0, __shfl_xor_sync(0xFFFFFFFFu, mx0, 1));
        mx0 = fmaxf(mx0, __shfl_xor_sync(0xFFFFFFFFu, mx0, 2));
        mx1 = fmaxf(mx1, __shfl_xor_sync(0xFFFFFFFFu, mx1, 1));
        mx1 = fmaxf(mx1, __shfl_xor_sync(0xFFFFFFFFu, mx1, 2));

        float mn0 = fmaxf(m0, mx0), mn1 = fmaxf(m1, mx1);
        float al0 = exp2f(m0 - mn0), al1 = exp2f(m1 - mn1);
        m0 = mn0; m1 = mn1;

        float sum0 = 0.f, sum1 = 0.f;
        #pragma unroll
        for (int nt = 0; nt < 8; nt++) {
            s[nt][0] = exp2f(s[nt][0] - m0);
            s[nt][1] = exp2f(s[nt][1] - m0);
            s[nt][2] = exp2f(s[nt][2] - m1);
            s[nt][3] = exp2f(s[nt][3] - m1);
            sum0 += s[nt][0] + s[nt][1];
            sum1 += s[nt][2] + s[nt][3];
        }
        sum0 += __shfl_xor_sync(0xFFFFFFFFu, sum0, 1);
        sum0 += __shfl_xor_sync(0xFFFFFFFFu, sum0, 2);
        sum1 += __shfl_xor_sync(0xFFFFFFFFu, sum1, 1);
        sum1 += __shfl_xor_sync(0xFFFFFFFFu, sum1, 2);
        l0 = l0 * al0 + sum0;
        l1 = l1 * al1 + sum1;

        #pragma unroll
        for (int nt = 0; nt < 8; nt++) {
            o[nt][0] *= al0; o[nt][1] *= al0;
            o[nt][2] *= al1; o[nt][3] *= al1;
        }

        // O += P V : P from registers; V via ldmatrix.trans
        #pragma unroll
        for (int kc = 0; kc < 4; kc++) {
            uint32_t ap[4];
            ap[0] = pack_h2(s[2*kc  ][0], s[2*kc  ][1]);
            ap[1] = pack_h2(s[2*kc  ][2], s[2*kc  ][3]);
            ap[2] = pack_h2(s[2*kc+1][0], s[2*kc+1][1]);
            ap[3] = pack_h2(s[2*kc+1][2], s[2*kc+1][3]);
            #pragma unroll
            for (int i = 0; i < 4; i++) {
                uint32_t bq[4];
                ldsm_x4_t(bq, sVb + b_lo_v +
                          (uint32_t)(((kc * 16) * KST + i * 16) * 2));
                mma_f16(o[2*i],   ap, bq);
                mma_f16(o[2*i+1], ap, bq + 2);
            }
        }
    }

    // normalize + fp16 store
    float inv0 = 1.0f / l0, inv1 = 1.0f / l1;
    __half* O0 = out + ((size_t)(b * SEQ + r0)) * DIMN + h * HD;
    __half* O8 = O0 + 8 * DIMN;
    #pragma unroll
    for (int nt = 0; nt < 8; nt++) {
        int col = nt * 8 + 2 * qc;
        *reinterpret_cast<__half2*>(O0 + col) =
            __floats2half2_rn(o[nt][0] * inv0, o[nt][1] * inv0);
        *reinterpret_cast<__half2*>(O8 + col) =
            __floats2half2_rn(o[nt][2] * inv1, o[nt][3] * inv1);
    }
}

// ---------------- launch ----------------------------------------------------
extern "C" void kernel_launch(void* const* d_in, const int* in_sizes, int n_in,
                              void* d_out, int out_size)
{
    (void)in_sizes; (void)n_in; (void)out_size;
    const float* x      = (const float*)d_in[0];
    const float* w_qkv  = (const float*)d_in[1];
    const float* w_proj = (const float*)d_in[2];
    const float* b_proj = (const float*)d_in[3];
    const float* ln1_g  = (const float*)d_in[4];
    const float* ln1_b  = (const float*)d_in[5];
    const float* w1     = (const float*)d_in[6];
    const float* b1     = (const float*)d_in[7];
    const float* w2     = (const float*)d_in[8];
    const float* b2     = (const float*)d_in[9];
    const float* ln2_g  = (const float*)d_in[10];
    const float* ln2_b  = (const float*)d_in[11];
    float* out = (float*)d_out;

    __half *p_h, *p_qkv, *p_o, *p_ffn, *p_wq, *p_wp, *p_w1, *p_w2;
    float *p_x1;
    cudaGetSymbolAddress((void**)&p_h,   g_h);
    cudaGetSymbolAddress((void**)&p_qkv, g_qkv);
    cudaGetSymbolAddress((void**)&p_o,   g_o);
    cudaGetSymbolAddress((void**)&p_x1,  g_x1);
    cudaGetSymbolAddress((void**)&p_ffn, g_ffn);
    cudaGetSymbolAddress((void**)&p_wq,  g_wq);
    cudaGetSymbolAddress((void**)&p_wp,  g_wp);
    cudaGetSymbolAddress((void**)&p_w1,  g_w1t);
    cudaGetSymbolAddress((void**)&p_w2,  g_w2t);

    cudaFuncSetAttribute(gemm_f16<0,1>, cudaFuncAttributeMaxDynamicSharedMemorySize, GEMM_SMEM);
    cudaFuncSetAttribute(gemm_f16<1,0>, cudaFuncAttributeMaxDynamicSharedMemorySize, GEMM_SMEM);
    cudaFuncSetAttribute(gemm_f16<2,1>, cudaFuncAttributeMaxDynamicSharedMemorySize, GEMM_SMEM);

    // 0) all weight transposes + fp16 convert in ONE launch
    cvt_all<<<T_ALL, dim3(32,8)>>>(w_qkv, w_proj, w1, w2, p_wq, p_wp, p_w1, p_w2);

    // 1) LN1 (fp16 out)
    ln_kernel<<<MROWS, 256>>>(x, ln1_g, ln1_b, p_h);
    // 2) QKV projection (fp16 out; Q columns pre-scaled by 0.125*log2e)
    gemm_f16<0,1><<<dim3(3*DIMN/128, MROWS/256), 512, GEMM_SMEM>>>(p_h, p_wq, nullptr, nullptr, p_qkv, DIMN, 3*DIMN);
    // 3) attention (fp16 out)
    attn_f16<<<dim3(BB*NHEADS, SEQ/128), 256>>>(p_qkv, p_o);
    // 4) output projection + bias + residual (fp32 out)
    gemm_f16<1,0><<<dim3(DIMN/128, MROWS/256), 512, GEMM_SMEM>>>(p_o, p_wp, b_proj, x, p_x1, DIMN, DIMN);
    // 5) LN2 (fp16 out)
    ln_kernel<<<MROWS, 256>>>(p_x1, ln2_g, ln2_b, p_h);
    // 6) FFN up + GELU (fp16 out)
    gemm_f16<2,1><<<dim3(HIDDEN/128, MROWS/256), 512, GEMM_SMEM>>>(p_h, p_w1, b1, nullptr, p_ffn, DIMN, HIDDEN);
    // 7) FFN down + bias + residual (fp32 out)
    gemm_f16<1,0><<<dim3(DIMN/128, MROWS/256), 512, GEMM_SMEM>>>(p_ffn, p_w2, b2, p_x1, out, HIDDEN, DIMN);
}